// round 13
// baseline (speedup 1.0000x reference)
#include <cuda_runtime.h>
#include <cuda_bf16.h>
#include <math.h>

#define NN    50000
#define NNP   50048    // padded to 128
#define F_IN  256
#define D_HID 64
#define NH    8
#define HD    512      // NH * D_HID
#define NC    10
#define MAXE  850000

// ---------------- scratch (device globals: no allocs allowed) ----------------
__device__ __nv_bfloat16 g_h1b[NNP * HD];   // layer-1 features bf16 (51.2 MB)
__device__ float g_xcat[NN * HD];           // layer-1 output / layer-2 input
__device__ __nv_bfloat16 g_Ahi[NNP * F_IN]; // x hi plane
__device__ __nv_bfloat16 g_Alo[NNP * F_IN]; // x lo plane
__device__ __nv_bfloat16 g_Bhi[HD * F_IN];  // W packed [n=h*64+d][k], bf16 hi
__device__ __nv_bfloat16 g_Blo[HD * F_IN];  // bf16 lo residual
__device__ float g_s1[NN * NH];
__device__ float g_s2[NN * NH];
__device__ int   g_cnt[NN];
__device__ int   g_rowstart[NN + 1];
__device__ int   g_cursor[NN];
__device__ int   g_incl[NN];
__device__ int   g_bsum[64];
__device__ int   g_boff[64];
__device__ int   g_edst[MAXE];
__device__ float g_h2[NN * 16];
__device__ float g_t1[NN];
__device__ float g_t2[NN];

__device__ __forceinline__ float eluf(float x) { return x > 0.f ? x : expm1f(x); }
__device__ __forceinline__ float att_e(float sc) {
    float lk = sc > 0.f ? sc : 0.2f * sc;
    return expf(-lk);
}

// ---------------- small utility kernels ----------------
__global__ void k_zero_cnt() {
    int i = blockIdx.x * blockDim.x + threadIdx.x;
    if (i < NN) g_cnt[i] = 0;
}

// x[NN,256] fp32 -> bf16 hi/lo planes
__global__ void k_convA(const float* __restrict__ x) {
    int i = blockIdx.x * blockDim.x + threadIdx.x;
    if (i >= NN * F_IN / 4) return;
    float4 v = *(const float4*)(x + (size_t)i * 4);
    float vs[4] = {v.x, v.y, v.z, v.w};
    __nv_bfloat16 hi[4], lo[4];
    #pragma unroll
    for (int e = 0; e < 4; e++) {
        hi[e] = __float2bfloat16(vs[e]);
        lo[e] = __float2bfloat16(vs[e] - __bfloat162float(hi[e]));
    }
    *(uint2*)(g_Ahi + (size_t)i * 4) = *(uint2*)hi;
    *(uint2*)(g_Alo + (size_t)i * 4) = *(uint2*)lo;
}

// pack W_heads [H][F_IN][D_HID] -> bf16 hi/lo planes, layout [n][k]
__global__ void k_pack(const float* __restrict__ Wh) {
    int i = blockIdx.x * blockDim.x + threadIdx.x;
    if (i >= HD * F_IN) return;
    int n = i >> 8;
    int k = i & 255;
    int h = n >> 6;
    int d = n & 63;
    float w = Wh[h * (F_IN * D_HID) + k * D_HID + d];
    __nv_bfloat16 hi = __float2bfloat16(w);
    float lo = w - __bfloat162float(hi);
    g_Bhi[i] = hi;
    g_Blo[i] = __float2bfloat16(lo);
}

__global__ void k_count(const int* __restrict__ src, int E) {
    int e = blockIdx.x * blockDim.x + threadIdx.x;
    if (e < E) atomicAdd(&g_cnt[src[e]], 1);
}

__global__ void k_scan1() {
    __shared__ int sh[1024];
    int b = blockIdx.x, tid = threadIdx.x;
    int i = b * 1024 + tid;
    int v = (i < NN) ? g_cnt[i] : 0;
    sh[tid] = v;
    __syncthreads();
    #pragma unroll
    for (int off = 1; off < 1024; off <<= 1) {
        int t = (tid >= off) ? sh[tid - off] : 0;
        __syncthreads();
        sh[tid] += t;
        __syncthreads();
    }
    if (i < NN) g_incl[i] = sh[tid];
    if (tid == 1023) g_bsum[b] = sh[tid];
}

__global__ void k_scan2() {
    __shared__ int sh[64];
    int tid = threadIdx.x;
    const int nb = (NN + 1023) / 1024;
    int v = (tid < nb) ? g_bsum[tid] : 0;
    sh[tid] = v;
    __syncthreads();
    #pragma unroll
    for (int off = 1; off < 64; off <<= 1) {
        int t = (tid >= off) ? sh[tid - off] : 0;
        __syncthreads();
        sh[tid] += t;
        __syncthreads();
    }
    g_boff[tid] = sh[tid] - v;
}

__global__ void k_scan3() {
    int i = blockIdx.x * blockDim.x + threadIdx.x;
    if (i >= NN) return;
    int incl = g_incl[i] + g_boff[i >> 10];
    g_rowstart[i + 1] = incl;
    g_cursor[i] = incl - g_cnt[i];
    if (i == 0) g_rowstart[0] = 0;
}

__global__ void k_scatter(const int* __restrict__ src, const int* __restrict__ dst, int E) {
    int e = blockIdx.x * blockDim.x + threadIdx.x;
    if (e < E) {
        int s = src[e];
        int p = atomicAdd(&g_cursor[s], 1);
        g_edst[p] = dst[e];
    }
}

// ---------------- layer-1 GEMM: split-bf16 3xMMA, cp.async double-buffered ---
#define BM 128
#define BN 128
#define BK 32
#define PADH 40
#define PLANE (BM * PADH)
#define STAGE_BYTES (4 * PLANE * 2)   // 40960
#define NTILES (F_IN / BK)

__device__ __forceinline__ void mma16816(float* c, const unsigned* a, const unsigned* b) {
    asm volatile(
        "mma.sync.aligned.m16n8k16.row.col.f32.bf16.bf16.f32 "
        "{%0,%1,%2,%3}, {%4,%5,%6,%7}, {%8,%9}, {%0,%1,%2,%3};\n"
        : "+f"(c[0]), "+f"(c[1]), "+f"(c[2]), "+f"(c[3])
        : "r"(a[0]), "r"(a[1]), "r"(a[2]), "r"(a[3]), "r"(b[0]), "r"(b[1]));
}

__device__ __forceinline__ void cpa16(unsigned dst, const void* src) {
    asm volatile("cp.async.cg.shared.global [%0], [%1], 16;\n" :: "r"(dst), "l"(src));
}
__device__ __forceinline__ void cpa_commit() {
    asm volatile("cp.async.commit_group;\n");
}
template <int N>
__device__ __forceinline__ void cpa_wait() {
    asm volatile("cp.async.wait_group %0;\n" :: "n"(N));
}

__global__ void __launch_bounds__(256, 2) k_gemm1_mma(const float* __restrict__ ah) {
    extern __shared__ __nv_bfloat16 smem[];

    const int tid = threadIdx.x;
    const int lane = tid & 31;
    const int warp = tid >> 5;
    const int wm = warp & 3;
    const int wn = warp >> 2;
    const int rowBase = blockIdx.y * BM;
    const int colBase = blockIdx.x * BN;

    const int gr = lane >> 2;
    const int t2 = (lane & 3) * 2;

    float acc[2][8][4];
    #pragma unroll
    for (int i = 0; i < 2; i++)
        #pragma unroll
        for (int j = 0; j < 8; j++)
            #pragma unroll
            for (int q = 0; q < 4; q++) acc[i][j][q] = 0.f;

    const int c0 = tid, c1 = tid + 256;
    const int r0c = c0 >> 2, s0c = (c0 & 3) * 8;
    const int r1c = c1 >> 2, s1c = (c1 & 3) * 8;

    unsigned sbase = (unsigned)__cvta_generic_to_shared(smem);

    auto load_stage = [&](int it, int buf) {
        int k0 = it * BK;
        unsigned b = sbase + buf * STAGE_BYTES;
        const __nv_bfloat16* a0h = g_Ahi + (size_t)(rowBase + r0c) * F_IN + k0 + s0c;
        const __nv_bfloat16* a1h = g_Ahi + (size_t)(rowBase + r1c) * F_IN + k0 + s1c;
        const __nv_bfloat16* a0l = g_Alo + (size_t)(rowBase + r0c) * F_IN + k0 + s0c;
        const __nv_bfloat16* a1l = g_Alo + (size_t)(rowBase + r1c) * F_IN + k0 + s1c;
        cpa16(b + (r0c * PADH + s0c) * 2, a0h);
        cpa16(b + (r1c * PADH + s1c) * 2, a1h);
        cpa16(b + (PLANE + r0c * PADH + s0c) * 2, a0l);
        cpa16(b + (PLANE + r1c * PADH + s1c) * 2, a1l);
        const __nv_bfloat16* b0h = g_Bhi + (size_t)(colBase + r0c) * F_IN + k0 + s0c;
        const __nv_bfloat16* b1h = g_Bhi + (size_t)(colBase + r1c) * F_IN + k0 + s1c;
        const __nv_bfloat16* b0l = g_Blo + (size_t)(colBase + r0c) * F_IN + k0 + s0c;
        const __nv_bfloat16* b1l = g_Blo + (size_t)(colBase + r1c) * F_IN + k0 + s1c;
        cpa16(b + (2 * PLANE + r0c * PADH + s0c) * 2, b0h);
        cpa16(b + (2 * PLANE + r1c * PADH + s1c) * 2, b1h);
        cpa16(b + (3 * PLANE + r0c * PADH + s0c) * 2, b0l);
        cpa16(b + (3 * PLANE + r1c * PADH + s1c) * 2, b1l);
    };

    load_stage(0, 0);
    cpa_commit();

    for (int it = 0; it < NTILES; it++) {
        if (it + 1 < NTILES) {
            load_stage(it + 1, (it + 1) & 1);
            cpa_commit();
            cpa_wait<1>();
        } else {
            cpa_wait<0>();
        }
        __syncthreads();

        const __nv_bfloat16* As_hi = smem + (it & 1) * (STAGE_BYTES / 2);
        const __nv_bfloat16* As_lo = As_hi + PLANE;
        const __nv_bfloat16* Bs_hi = As_lo + PLANE;
        const __nv_bfloat16* Bs_lo = Bs_hi + PLANE;

        #pragma unroll
        for (int kk = 0; kk < BK; kk += 16) {
            unsigned ahi[2][4], alo[2][4];
            #pragma unroll
            for (int mi = 0; mi < 2; mi++) {
                int base = (wm * 32 + mi * 16 + gr) * PADH + kk + t2;
                ahi[mi][0] = *(const unsigned*)&As_hi[base];
                ahi[mi][1] = *(const unsigned*)&As_hi[base + 8 * PADH];
                ahi[mi][2] = *(const unsigned*)&As_hi[base + 8];
                ahi[mi][3] = *(const unsigned*)&As_hi[base + 8 * PADH + 8];
                alo[mi][0] = *(const unsigned*)&As_lo[base];
                alo[mi][1] = *(const unsigned*)&As_lo[base + 8 * PADH];
                alo[mi][2] = *(const unsigned*)&As_lo[base + 8];
                alo[mi][3] = *(const unsigned*)&As_lo[base + 8 * PADH + 8];
            }
            #pragma unroll
            for (int ni = 0; ni < 8; ni++) {
                int nb = (wn * 64 + ni * 8 + gr) * PADH + kk + t2;
                unsigned bhi[2], blo[2];
                bhi[0] = *(const unsigned*)&Bs_hi[nb];
                bhi[1] = *(const unsigned*)&Bs_hi[nb + 8];
                blo[0] = *(const unsigned*)&Bs_lo[nb];
                blo[1] = *(const unsigned*)&Bs_lo[nb + 8];
                #pragma unroll
                for (int mi = 0; mi < 2; mi++) {
                    mma16816(acc[mi][ni], ahi[mi], bhi);
                    mma16816(acc[mi][ni], ahi[mi], blo);
                    mma16816(acc[mi][ni], alo[mi], bhi);
                }
            }
        }
        __syncthreads();
    }

    // ---- epilogue: store bf16 h1, fused per-(row,head) score dots ----
    const int h = (colBase >> 6) + wn;
    #pragma unroll
    for (int mi = 0; mi < 2; mi++) {
        int r0 = rowBase + wm * 32 + mi * 16 + gr;
        int r1 = r0 + 8;
        float p1a = 0.f, p2a = 0.f, p1b = 0.f, p2b = 0.f;
        #pragma unroll
        for (int ni = 0; ni < 8; ni++) {
            int col = colBase + wn * 64 + ni * 8 + t2;
            if (r0 < NN)
                *(__nv_bfloat162*)(g_h1b + (size_t)r0 * HD + col) =
                    __float22bfloat162_rn(make_float2(acc[mi][ni][0], acc[mi][ni][1]));
            if (r1 < NN)
                *(__nv_bfloat162*)(g_h1b + (size_t)r1 * HD + col) =
                    __float22bfloat162_rn(make_float2(acc[mi][ni][2], acc[mi][ni][3]));
            float2 a1v = *(const float2*)(ah + h * 128 + ni * 8 + t2);
            float2 a2v = *(const float2*)(ah + h * 128 + 64 + ni * 8 + t2);
            p1a += acc[mi][ni][0] * a1v.x + acc[mi][ni][1] * a1v.y;
            p2a += acc[mi][ni][0] * a2v.x + acc[mi][ni][1] * a2v.y;
            p1b += acc[mi][ni][2] * a1v.x + acc[mi][ni][3] * a1v.y;
            p2b += acc[mi][ni][2] * a2v.x + acc[mi][ni][3] * a2v.y;
        }
        #pragma unroll
        for (int off = 1; off < 4; off <<= 1) {
            p1a += __shfl_xor_sync(0xffffffffu, p1a, off);
            p2a += __shfl_xor_sync(0xffffffffu, p2a, off);
            p1b += __shfl_xor_sync(0xffffffffu, p1b, off);
            p2b += __shfl_xor_sync(0xffffffffu, p2b, off);
        }
        if ((lane & 3) == 0) {
            if (r0 < NN) { g_s1[r0 * NH + h] = p1a; g_s2[r0 * NH + h] = p2a; }
            if (r1 < NN) { g_s1[r1 * NH + h] = p1b; g_s2[r1 * NH + h] = p2b; }
        }
    }
}

// ------- layer-1 aggregation, FUSED attention: warp per (node, head) --------
// Warp w of block n handles head w. Lanes 0-3 compute e for 4 edges and
// broadcast; 8 lanes x 16B gather each edge's 128B head slice (4 rows in
// flight per warp).
__global__ void __launch_bounds__(256) k_agg1f() {
    int n = blockIdx.x;
    int w = threadIdx.x >> 5;      // head
    int lane = threadIdx.x & 31;
    int es = lane >> 3;            // edge slot 0..3
    int dd = lane & 7;             // dim octet
    int start = g_rowstart[n];
    int end   = g_rowstart[n + 1];
    float s1v = g_s1[n * NH + w];

    float acc[8];
    #pragma unroll
    for (int i = 0; i < 8; i++) acc[i] = 0.f;
    float rs = 0.f;

    for (int p0 = start; p0 < end; p0 += 4) {
        int rem = end - p0;
        int dl = 0; float el = 0.f;
        if (lane < 4 && lane < rem) {
            dl = g_edst[p0 + lane];
            el = att_e(s1v + g_s2[dl * NH + w]);
        }
        int   d = __shfl_sync(0xffffffffu, dl, es);
        float e = __shfl_sync(0xffffffffu, el, es);
        if (es < rem) {
            uint4 raw = *(const uint4*)(g_h1b + (size_t)d * HD + w * 64 + dd * 8);
            float2 f0 = __bfloat1622float2(*(__nv_bfloat162*)&raw.x);
            float2 f1 = __bfloat1622float2(*(__nv_bfloat162*)&raw.y);
            float2 f2 = __bfloat1622float2(*(__nv_bfloat162*)&raw.z);
            float2 f3 = __bfloat1622float2(*(__nv_bfloat162*)&raw.w);
            acc[0] += e * f0.x; acc[1] += e * f0.y;
            acc[2] += e * f1.x; acc[3] += e * f1.y;
            acc[4] += e * f2.x; acc[5] += e * f2.y;
            acc[6] += e * f3.x; acc[7] += e * f3.y;
        }
        rs += el;   // nonzero only on lanes 0-3
    }

    // reduce the 4 edge slots (lanes xor 8, 16)
    #pragma unroll
    for (int i = 0; i < 8; i++) {
        acc[i] += __shfl_xor_sync(0xffffffffu, acc[i], 8);
        acc[i] += __shfl_xor_sync(0xffffffffu, acc[i], 16);
    }
    rs += __shfl_xor_sync(0xffffffffu, rs, 1);
    rs += __shfl_xor_sync(0xffffffffu, rs, 2);
    rs  = __shfl_sync(0xffffffffu, rs, 0);

    if (lane < 8) {
        float inv = 1.f / rs;
        float4 o0, o1;
        o0.x = eluf(acc[0] * inv); o0.y = eluf(acc[1] * inv);
        o0.z = eluf(acc[2] * inv); o0.w = eluf(acc[3] * inv);
        o1.x = eluf(acc[4] * inv); o1.y = eluf(acc[5] * inv);
        o1.z = eluf(acc[6] * inv); o1.w = eluf(acc[7] * inv);
        float* op = g_xcat + (size_t)n * HD + w * 64 + lane * 8;
        *(float4*)op = o0;
        *(float4*)(op + 4) = o1;
    }
}

// ---------------- layer-2 GEMM + score dots (warp per node) ------------------
__global__ void k_gemm2(const float* __restrict__ Wo, const float* __restrict__ ao) {
    __shared__ float Ws[HD * NC];
    __shared__ float as_[2 * NC];
    int tid = threadIdx.x;
    for (int i = tid; i < HD * NC; i += 256) Ws[i] = Wo[i];
    if (tid < 2 * NC) as_[tid] = ao[tid];
    __syncthreads();
    int warp = tid >> 5;
    int lane = tid & 31;
    int n = blockIdx.x * 8 + warp;
    if (n >= NN) return;
    float acc[NC];
    #pragma unroll
    for (int c = 0; c < NC; c++) acc[c] = 0.f;
    const float* xp = g_xcat + (size_t)n * HD;
    for (int k0 = 0; k0 < HD; k0 += 32) {
        float xv = xp[k0 + lane];
        const float* wrow = Ws + (k0 + lane) * NC;
        #pragma unroll
        for (int c = 0; c < NC; c++) acc[c] += xv * wrow[c];
    }
    #pragma unroll
    for (int c = 0; c < NC; c++)
        #pragma unroll
        for (int off = 16; off; off >>= 1)
            acc[c] += __shfl_xor_sync(0xffffffffu, acc[c], off);
    if (lane == 0) {
        float s1 = 0.f, s2 = 0.f;
        #pragma unroll
        for (int c = 0; c < NC; c++) {
            g_h2[n * 16 + c] = acc[c];
            s1 += acc[c] * as_[c];
            s2 += acc[c] * as_[NC + c];
        }
        g_t1[n] = s1;
        g_t2[n] = s2;
    }
}

// ------- layer-2 aggregation, FUSED attention + elu + log_softmax -----------
__global__ void k_agg2f(float* __restrict__ out) {
    int warp = (blockIdx.x * blockDim.x + threadIdx.x) >> 5;
    int lane = threadIdx.x & 31;
    if (warp >= NN) return;
    int n = warp;
    int start = g_rowstart[n];
    int end   = g_rowstart[n + 1];
    float t1n = g_t1[n];
    float acc = 0.f, rs = 0.f;
    for (int p0 = start; p0 < end; p0 += 32) {
        int p = p0 + lane;
        float ev = 0.f; int d = 0;
        if (p < end) {
            d = g_edst[p];
            ev = att_e(t1n + g_t2[d]);
        }
        rs += ev;
        int cnt = min(32, end - p0);
        for (int j = 0; j < cnt; j++) {
            float evj = __shfl_sync(0xffffffffu, ev, j);
            int   dj  = __shfl_sync(0xffffffffu, d, j);
            if (lane < NC) acc += evj * g_h2[dj * 16 + lane];
        }
    }
    #pragma unroll
    for (int off = 16; off; off >>= 1)
        rs += __shfl_xor_sync(0xffffffffu, rs, off);
    float v = (lane < NC) ? eluf(acc / rs) : -1e30f;
    float m = v;
    #pragma unroll
    for (int off = 16; off; off >>= 1) m = fmaxf(m, __shfl_xor_sync(0xffffffffu, m, off));
    float ex = (lane < NC) ? expf(v - m) : 0.f;
    float sm = ex;
    #pragma unroll
    for (int off = 16; off; off >>= 1) sm += __shfl_xor_sync(0xffffffffu, sm, off);
    if (lane < NC) out[(size_t)n * NC + lane] = v - m - logf(sm);
}

// ---------------- launcher ----------------
extern "C" void kernel_launch(void* const* d_in, const int* in_sizes, int n_in,
                              void* d_out, int out_size) {
    const float* x    = (const float*)d_in[0];
    const int*   esrc = (const int*)d_in[1];
    const int*   edst = (const int*)d_in[2];
    const float* Wh   = (const float*)d_in[3];
    const float* ah   = (const float*)d_in[4];
    const float* Wo   = (const float*)d_in[5];
    const float* ao   = (const float*)d_in[6];
    float* out = (float*)d_out;
    const int E = in_sizes[1];

    cudaFuncSetAttribute(k_gemm1_mma,
                         cudaFuncAttributeMaxDynamicSharedMemorySize,
                         2 * STAGE_BYTES);

    k_zero_cnt<<<(NN + 255) / 256, 256>>>();
    k_convA<<<(NN * F_IN / 4 + 255) / 256, 256>>>(x);
    k_pack<<<(HD * F_IN + 255) / 256, 256>>>(Wh);
    k_count<<<(E + 255) / 256, 256>>>(esrc, E);
    k_gemm1_mma<<<dim3(HD / BN, NNP / BM), 256, 2 * STAGE_BYTES>>>(ah);
    k_scan1<<<(NN + 1023) / 1024, 1024>>>();
    k_scan2<<<1, 64>>>();
    k_scan3<<<(NN + 255) / 256, 256>>>();
    k_scatter<<<(E + 255) / 256, 256>>>(esrc, edst, E);
    k_agg1f<<<NN, 256>>>();
    k_gemm2<<<(NN + 7) / 8, 256>>>(Wo, ao);
    k_agg2f<<<(NN + 7) / 8, 256>>>(out);
}

// round 16
// speedup vs baseline: 1.1612x; 1.1612x over previous
#include <cuda_runtime.h>
#include <cuda_bf16.h>
#include <math.h>

#define NN    50000
#define NNP   50048    // padded to 128
#define F_IN  256
#define D_HID 64
#define NH    8
#define HD    512      // NH * D_HID
#define NC    10
#define MAXE  850000

// ---------------- scratch (device globals: no allocs allowed) ----------------
__device__ __nv_bfloat16 g_h1b[NNP * HD];   // layer-1 features bf16 (51.2 MB)
__device__ float g_xcat[NN * HD];           // layer-1 output / layer-2 input
__device__ __nv_bfloat16 g_Ahi[NNP * F_IN]; // x hi plane
__device__ __nv_bfloat16 g_Alo[NNP * F_IN]; // x lo plane
__device__ __nv_bfloat16 g_Bhi[HD * F_IN];  // W packed [n=h*64+d][k], bf16 hi
__device__ __nv_bfloat16 g_Blo[HD * F_IN];  // bf16 lo residual
__device__ float g_s1[NN * NH];
__device__ float g_s2[NN * NH];
__device__ int   g_cnt[NN];
__device__ int   g_rowstart[NN + 1];
__device__ int   g_cursor[NN];
__device__ int   g_incl[NN];
__device__ int   g_bsum[64];
__device__ int   g_boff[64];
__device__ int   g_edst[MAXE];
__device__ float g_eval1[MAXE * NH];        // per-(edge,head) attention weights
__device__ float g_eval2[MAXE];
__device__ float g_h2[NN * 16];
__device__ float g_t1[NN];
__device__ float g_t2[NN];

__device__ __forceinline__ float eluf(float x) { return x > 0.f ? x : expm1f(x); }
__device__ __forceinline__ float att_e(float sc) {
    float lk = sc > 0.f ? sc : 0.2f * sc;
    return expf(-lk);
}

// ---------------- small utility kernels ----------------
__global__ void k_zero_cnt() {
    int i = blockIdx.x * blockDim.x + threadIdx.x;
    if (i < NN) g_cnt[i] = 0;
}

// x[NN,256] fp32 -> bf16 hi/lo planes
__global__ void k_convA(const float* __restrict__ x) {
    int i = blockIdx.x * blockDim.x + threadIdx.x;
    if (i >= NN * F_IN / 4) return;
    float4 v = *(const float4*)(x + (size_t)i * 4);
    float vs[4] = {v.x, v.y, v.z, v.w};
    __nv_bfloat16 hi[4], lo[4];
    #pragma unroll
    for (int e = 0; e < 4; e++) {
        hi[e] = __float2bfloat16(vs[e]);
        lo[e] = __float2bfloat16(vs[e] - __bfloat162float(hi[e]));
    }
    *(uint2*)(g_Ahi + (size_t)i * 4) = *(uint2*)hi;
    *(uint2*)(g_Alo + (size_t)i * 4) = *(uint2*)lo;
}

// pack W_heads [H][F_IN][D_HID] -> bf16 hi/lo planes, layout [n][k]
__global__ void k_pack(const float* __restrict__ Wh) {
    int i = blockIdx.x * blockDim.x + threadIdx.x;
    if (i >= HD * F_IN) return;
    int n = i >> 8;
    int k = i & 255;
    int h = n >> 6;
    int d = n & 63;
    float w = Wh[h * (F_IN * D_HID) + k * D_HID + d];
    __nv_bfloat16 hi = __float2bfloat16(w);
    float lo = w - __bfloat162float(hi);
    g_Bhi[i] = hi;
    g_Blo[i] = __float2bfloat16(lo);
}

__global__ void k_count(const int* __restrict__ src, int E) {
    int e = blockIdx.x * blockDim.x + threadIdx.x;
    if (e < E) atomicAdd(&g_cnt[src[e]], 1);
}

__global__ void k_scan1() {
    __shared__ int sh[1024];
    int b = blockIdx.x, tid = threadIdx.x;
    int i = b * 1024 + tid;
    int v = (i < NN) ? g_cnt[i] : 0;
    sh[tid] = v;
    __syncthreads();
    #pragma unroll
    for (int off = 1; off < 1024; off <<= 1) {
        int t = (tid >= off) ? sh[tid - off] : 0;
        __syncthreads();
        sh[tid] += t;
        __syncthreads();
    }
    if (i < NN) g_incl[i] = sh[tid];
    if (tid == 1023) g_bsum[b] = sh[tid];
}

__global__ void k_scan2() {
    __shared__ int sh[64];
    int tid = threadIdx.x;
    const int nb = (NN + 1023) / 1024;
    int v = (tid < nb) ? g_bsum[tid] : 0;
    sh[tid] = v;
    __syncthreads();
    #pragma unroll
    for (int off = 1; off < 64; off <<= 1) {
        int t = (tid >= off) ? sh[tid - off] : 0;
        __syncthreads();
        sh[tid] += t;
        __syncthreads();
    }
    g_boff[tid] = sh[tid] - v;
}

__global__ void k_scan3() {
    int i = blockIdx.x * blockDim.x + threadIdx.x;
    if (i >= NN) return;
    int incl = g_incl[i] + g_boff[i >> 10];
    g_rowstart[i + 1] = incl;
    g_cursor[i] = incl - g_cnt[i];
    if (i == 0) g_rowstart[0] = 0;
}

__global__ void k_scatter(const int* __restrict__ src, const int* __restrict__ dst, int E) {
    int e = blockIdx.x * blockDim.x + threadIdx.x;
    if (e < E) {
        int s = src[e];
        int p = atomicAdd(&g_cursor[s], 1);
        g_edst[p] = dst[e];
    }
}

// ---------------- layer-1 GEMM: split-bf16 3xMMA, cp.async 3-stage pipeline --
#define BM 128
#define BN 128
#define BK 32
#define PADH 40
#define PLANE (BM * PADH)
#define STAGE_BYTES (4 * PLANE * 2)   // 40960
#define NSTAGE 3
#define NTILES (F_IN / BK)            // 8

__device__ __forceinline__ void mma16816(float* c, const unsigned* a, const unsigned* b) {
    asm volatile(
        "mma.sync.aligned.m16n8k16.row.col.f32.bf16.bf16.f32 "
        "{%0,%1,%2,%3}, {%4,%5,%6,%7}, {%8,%9}, {%0,%1,%2,%3};\n"
        : "+f"(c[0]), "+f"(c[1]), "+f"(c[2]), "+f"(c[3])
        : "r"(a[0]), "r"(a[1]), "r"(a[2]), "r"(a[3]), "r"(b[0]), "r"(b[1]));
}

__device__ __forceinline__ void cpa16(unsigned dst, const void* src) {
    asm volatile("cp.async.cg.shared.global [%0], [%1], 16;\n" :: "r"(dst), "l"(src));
}
__device__ __forceinline__ void cpa_commit() {
    asm volatile("cp.async.commit_group;\n");
}
template <int N>
__device__ __forceinline__ void cpa_wait() {
    asm volatile("cp.async.wait_group %0;\n" :: "n"(N));
}

__global__ void __launch_bounds__(256) k_gemm1_mma(const float* __restrict__ ah) {
    extern __shared__ __nv_bfloat16 smem[];

    const int tid = threadIdx.x;
    const int lane = tid & 31;
    const int warp = tid >> 5;
    const int wm = warp & 3;
    const int wn = warp >> 2;
    const int rowBase = blockIdx.y * BM;
    const int colBase = blockIdx.x * BN;

    const int gr = lane >> 2;
    const int t2 = (lane & 3) * 2;

    float acc[2][8][4];
    #pragma unroll
    for (int i = 0; i < 2; i++)
        #pragma unroll
        for (int j = 0; j < 8; j++)
            #pragma unroll
            for (int q = 0; q < 4; q++) acc[i][j][q] = 0.f;

    const int c0 = tid, c1 = tid + 256;
    const int r0c = c0 >> 2, s0c = (c0 & 3) * 8;
    const int r1c = c1 >> 2, s1c = (c1 & 3) * 8;

    unsigned sbase = (unsigned)__cvta_generic_to_shared(smem);

    auto load_stage = [&](int it, int buf) {
        int k0 = it * BK;
        unsigned b = sbase + buf * STAGE_BYTES;
        const __nv_bfloat16* a0h = g_Ahi + (size_t)(rowBase + r0c) * F_IN + k0 + s0c;
        const __nv_bfloat16* a1h = g_Ahi + (size_t)(rowBase + r1c) * F_IN + k0 + s1c;
        const __nv_bfloat16* a0l = g_Alo + (size_t)(rowBase + r0c) * F_IN + k0 + s0c;
        const __nv_bfloat16* a1l = g_Alo + (size_t)(rowBase + r1c) * F_IN + k0 + s1c;
        cpa16(b + (r0c * PADH + s0c) * 2, a0h);
        cpa16(b + (r1c * PADH + s1c) * 2, a1h);
        cpa16(b + (PLANE + r0c * PADH + s0c) * 2, a0l);
        cpa16(b + (PLANE + r1c * PADH + s1c) * 2, a1l);
        const __nv_bfloat16* b0h = g_Bhi + (size_t)(colBase + r0c) * F_IN + k0 + s0c;
        const __nv_bfloat16* b1h = g_Bhi + (size_t)(colBase + r1c) * F_IN + k0 + s1c;
        const __nv_bfloat16* b0l = g_Blo + (size_t)(colBase + r0c) * F_IN + k0 + s0c;
        const __nv_bfloat16* b1l = g_Blo + (size_t)(colBase + r1c) * F_IN + k0 + s1c;
        cpa16(b + (2 * PLANE + r0c * PADH + s0c) * 2, b0h);
        cpa16(b + (2 * PLANE + r1c * PADH + s1c) * 2, b1h);
        cpa16(b + (3 * PLANE + r0c * PADH + s0c) * 2, b0l);
        cpa16(b + (3 * PLANE + r1c * PADH + s1c) * 2, b1l);
    };

    // prefetch 2 stages
    load_stage(0, 0);
    cpa_commit();
    load_stage(1, 1);
    cpa_commit();

    for (int it = 0; it < NTILES; it++) {
        if (it + 2 < NTILES) cpa_wait<1>(); else cpa_wait<0>();
        __syncthreads();

        const int buf = it % NSTAGE;
        const __nv_bfloat16* As_hi = smem + buf * (STAGE_BYTES / 2);
        const __nv_bfloat16* As_lo = As_hi + PLANE;
        const __nv_bfloat16* Bs_hi = As_lo + PLANE;
        const __nv_bfloat16* Bs_lo = Bs_hi + PLANE;

        #pragma unroll
        for (int kk = 0; kk < BK; kk += 16) {
            unsigned ahi[2][4], alo[2][4];
            #pragma unroll
            for (int mi = 0; mi < 2; mi++) {
                int base = (wm * 32 + mi * 16 + gr) * PADH + kk + t2;
                ahi[mi][0] = *(const unsigned*)&As_hi[base];
                ahi[mi][1] = *(const unsigned*)&As_hi[base + 8 * PADH];
                ahi[mi][2] = *(const unsigned*)&As_hi[base + 8];
                ahi[mi][3] = *(const unsigned*)&As_hi[base + 8 * PADH + 8];
                alo[mi][0] = *(const unsigned*)&As_lo[base];
                alo[mi][1] = *(const unsigned*)&As_lo[base + 8 * PADH];
                alo[mi][2] = *(const unsigned*)&As_lo[base + 8];
                alo[mi][3] = *(const unsigned*)&As_lo[base + 8 * PADH + 8];
            }
            #pragma unroll
            for (int ni = 0; ni < 8; ni++) {
                int nb = (wn * 64 + ni * 8 + gr) * PADH + kk + t2;
                unsigned bhi[2], blo[2];
                bhi[0] = *(const unsigned*)&Bs_hi[nb];
                bhi[1] = *(const unsigned*)&Bs_hi[nb + 8];
                blo[0] = *(const unsigned*)&Bs_lo[nb];
                blo[1] = *(const unsigned*)&Bs_lo[nb + 8];
                #pragma unroll
                for (int mi = 0; mi < 2; mi++) {
                    mma16816(acc[mi][ni], ahi[mi], bhi);
                    mma16816(acc[mi][ni], ahi[mi], blo);
                    mma16816(acc[mi][ni], alo[mi], bhi);
                }
            }
        }
        __syncthreads();

        if (it + 2 < NTILES) {
            load_stage(it + 2, (it + 2) % NSTAGE);
            cpa_commit();
        }
    }

    // ---- epilogue: store bf16 h1, fused per-(row,head) score dots ----
    const int h = (colBase >> 6) + wn;
    #pragma unroll
    for (int mi = 0; mi < 2; mi++) {
        int r0 = rowBase + wm * 32 + mi * 16 + gr;
        int r1 = r0 + 8;
        float p1a = 0.f, p2a = 0.f, p1b = 0.f, p2b = 0.f;
        #pragma unroll
        for (int ni = 0; ni < 8; ni++) {
            int col = colBase + wn * 64 + ni * 8 + t2;
            if (r0 < NN)
                *(__nv_bfloat162*)(g_h1b + (size_t)r0 * HD + col) =
                    __float22bfloat162_rn(make_float2(acc[mi][ni][0], acc[mi][ni][1]));
            if (r1 < NN)
                *(__nv_bfloat162*)(g_h1b + (size_t)r1 * HD + col) =
                    __float22bfloat162_rn(make_float2(acc[mi][ni][2], acc[mi][ni][3]));
            float2 a1v = *(const float2*)(ah + h * 128 + ni * 8 + t2);
            float2 a2v = *(const float2*)(ah + h * 128 + 64 + ni * 8 + t2);
            p1a += acc[mi][ni][0] * a1v.x + acc[mi][ni][1] * a1v.y;
            p2a += acc[mi][ni][0] * a2v.x + acc[mi][ni][1] * a2v.y;
            p1b += acc[mi][ni][2] * a1v.x + acc[mi][ni][3] * a1v.y;
            p2b += acc[mi][ni][2] * a2v.x + acc[mi][ni][3] * a2v.y;
        }
        #pragma unroll
        for (int off = 1; off < 4; off <<= 1) {
            p1a += __shfl_xor_sync(0xffffffffu, p1a, off);
            p2a += __shfl_xor_sync(0xffffffffu, p2a, off);
            p1b += __shfl_xor_sync(0xffffffffu, p1b, off);
            p2b += __shfl_xor_sync(0xffffffffu, p2b, off);
        }
        if ((lane & 3) == 0) {
            if (r0 < NN) { g_s1[r0 * NH + h] = p1a; g_s2[r0 * NH + h] = p2a; }
            if (r1 < NN) { g_s1[r1 * NH + h] = p1b; g_s2[r1 * NH + h] = p2b; }
        }
    }
}

// ---------------- per-(edge,head) attention weights: warp per node ----------
__global__ void k_eval1(int dummy) {
    int warp = (blockIdx.x * blockDim.x + threadIdx.x) >> 5;
    int lane = threadIdx.x & 31;
    if (warp >= NN) return;
    int n = warp;
    int start = g_rowstart[n];
    int deg   = g_rowstart[n + 1] - start;
    int h = lane & 7;
    float s1v = g_s1[n * NH + h];
    int total = deg * NH;
    for (int j = lane; j < total; j += 32) {
        int p = start + (j >> 3);
        int d = g_edst[p];
        float sc = s1v + g_s2[d * NH + h];
        g_eval1[(size_t)p * NH + h] = att_e(sc);
    }
}

// ---------------- layer-1 aggregation: 256 thr per node, bf16 gather --------
__global__ void __launch_bounds__(256) k_agg1() {
    __shared__ float s_red[128 * 5];
    int n = blockIdx.x;
    int t = threadIdx.x;
    int half = t >> 7;
    int tt = t & 127;
    int h = tt >> 4;
    int q = tt & 15;
    int start = g_rowstart[n];
    int end   = g_rowstart[n + 1];
    float4 acc = make_float4(0.f, 0.f, 0.f, 0.f);
    float rs = 0.f;
    #pragma unroll 2
    for (int p = start + half; p < end; p += 2) {
        int d = g_edst[p];
        float e = g_eval1[(size_t)p * NH + h];
        uint2 raw = *(const uint2*)(g_h1b + (size_t)d * HD + h * 64 + q * 4);
        float2 f0 = __bfloat1622float2(*(__nv_bfloat162*)&raw.x);
        float2 f1 = __bfloat1622float2(*(__nv_bfloat162*)&raw.y);
        acc.x += e * f0.x; acc.y += e * f0.y;
        acc.z += e * f1.x; acc.w += e * f1.y;
        rs += e;
    }
    if (half == 1) {
        float* sp = s_red + tt * 5;
        sp[0] = acc.x; sp[1] = acc.y; sp[2] = acc.z; sp[3] = acc.w; sp[4] = rs;
    }
    __syncthreads();
    if (half == 0) {
        float* sp = s_red + tt * 5;
        acc.x += sp[0]; acc.y += sp[1]; acc.z += sp[2]; acc.w += sp[3]; rs += sp[4];
        float inv = 1.f / rs;
        float4 o;
        o.x = eluf(acc.x * inv);
        o.y = eluf(acc.y * inv);
        o.z = eluf(acc.z * inv);
        o.w = eluf(acc.w * inv);
        *(float4*)(g_xcat + (size_t)n * HD + tt * 4) = o;
    }
}

// ---------------- layer-2 GEMM + score dots (warp per node) ------------------
__global__ void k_gemm2(const float* __restrict__ Wo, const float* __restrict__ ao) {
    __shared__ float Ws[HD * NC];
    __shared__ float as_[2 * NC];
    int tid = threadIdx.x;
    for (int i = tid; i < HD * NC; i += 256) Ws[i] = Wo[i];
    if (tid < 2 * NC) as_[tid] = ao[tid];
    __syncthreads();
    int warp = tid >> 5;
    int lane = tid & 31;
    int n = blockIdx.x * 8 + warp;
    if (n >= NN) return;
    float acc[NC];
    #pragma unroll
    for (int c = 0; c < NC; c++) acc[c] = 0.f;
    const float* xp = g_xcat + (size_t)n * HD;
    for (int k0 = 0; k0 < HD; k0 += 32) {
        float xv = xp[k0 + lane];
        const float* wrow = Ws + (k0 + lane) * NC;
        #pragma unroll
        for (int c = 0; c < NC; c++) acc[c] += xv * wrow[c];
    }
    #pragma unroll
    for (int c = 0; c < NC; c++)
        #pragma unroll
        for (int off = 16; off; off >>= 1)
            acc[c] += __shfl_xor_sync(0xffffffffu, acc[c], off);
    if (lane == 0) {
        float s1 = 0.f, s2 = 0.f;
        #pragma unroll
        for (int c = 0; c < NC; c++) {
            g_h2[n * 16 + c] = acc[c];
            s1 += acc[c] * as_[c];
            s2 += acc[c] * as_[NC + c];
        }
        g_t1[n] = s1;
        g_t2[n] = s2;
    }
}

__global__ void k_eval2(int dummy) {
    int warp = (blockIdx.x * blockDim.x + threadIdx.x) >> 5;
    int lane = threadIdx.x & 31;
    if (warp >= NN) return;
    int n = warp;
    int start = g_rowstart[n];
    int end   = g_rowstart[n + 1];
    float t1n = g_t1[n];
    for (int p = start + lane; p < end; p += 32) {
        g_eval2[p] = att_e(t1n + g_t2[g_edst[p]]);
    }
}

// ---------------- layer-2 aggregation + elu + log_softmax (warp per node) ----
__global__ void k_agg2(float* __restrict__ out) {
    int warp = (blockIdx.x * blockDim.x + threadIdx.x) >> 5;
    int lane = threadIdx.x & 31;
    if (warp >= NN) return;
    int n = warp;
    int start = g_rowstart[n];
    int end   = g_rowstart[n + 1];
    float acc = 0.f, rs = 0.f;
    for (int p = start; p < end; p++) {
        float ev = g_eval2[p];
        rs += ev;
        if (lane < NC) acc += ev * g_h2[g_edst[p] * 16 + lane];
    }
    float v = (lane < NC) ? eluf(acc / rs) : -1e30f;
    float m = v;
    #pragma unroll
    for (int off = 16; off; off >>= 1) m = fmaxf(m, __shfl_xor_sync(0xffffffffu, m, off));
    float ex = (lane < NC) ? expf(v - m) : 0.f;
    float sm = ex;
    #pragma unroll
    for (int off = 16; off; off >>= 1) sm += __shfl_xor_sync(0xffffffffu, sm, off);
    if (lane < NC) out[(size_t)n * NC + lane] = v - m - logf(sm);
}

// ---------------- launcher ----------------
extern "C" void kernel_launch(void* const* d_in, const int* in_sizes, int n_in,
                              void* d_out, int out_size) {
    const float* x    = (const float*)d_in[0];
    const int*   esrc = (const int*)d_in[1];
    const int*   edst = (const int*)d_in[2];
    const float* Wh   = (const float*)d_in[3];
    const float* ah   = (const float*)d_in[4];
    const float* Wo   = (const float*)d_in[5];
    const float* ao   = (const float*)d_in[6];
    float* out = (float*)d_out;
    const int E = in_sizes[1];

    cudaFuncSetAttribute(k_gemm1_mma,
                         cudaFuncAttributeMaxDynamicSharedMemorySize,
                         NSTAGE * STAGE_BYTES);

    // fork-join: CSR build runs in parallel with convA/pack/gemm1
    cudaStream_t s2;
    cudaEvent_t evFork, evJoin;
    cudaStreamCreateWithFlags(&s2, cudaStreamNonBlocking);
    cudaEventCreateWithFlags(&evFork, cudaEventDisableTiming);
    cudaEventCreateWithFlags(&evJoin, cudaEventDisableTiming);

    cudaEventRecord(evFork, 0);
    cudaStreamWaitEvent(s2, evFork, 0);

    // branch B (s2): CSR build
    k_zero_cnt<<<(NN + 255) / 256, 256, 0, s2>>>();
    k_count<<<(E + 255) / 256, 256, 0, s2>>>(esrc, E);
    k_scan1<<<(NN + 1023) / 1024, 1024, 0, s2>>>();
    k_scan2<<<1, 64, 0, s2>>>();
    k_scan3<<<(NN + 255) / 256, 256, 0, s2>>>();
    k_scatter<<<(E + 255) / 256, 256, 0, s2>>>(esrc, edst, E);
    cudaEventRecord(evJoin, s2);

    // branch A (stream 0): dense path
    k_convA<<<(NN * F_IN / 4 + 255) / 256, 256>>>(x);
    k_pack<<<(HD * F_IN + 255) / 256, 256>>>(Wh);
    k_gemm1_mma<<<dim3(HD / BN, NNP / BM), 256, NSTAGE * STAGE_BYTES>>>(ah);

    // join
    cudaStreamWaitEvent(0, evJoin, 0);

    k_eval1<<<(NN + 7) / 8, 256>>>(0);
    k_agg1<<<NN, 256>>>();
    k_gemm2<<<(NN + 7) / 8, 256>>>(Wo, ao);
    k_eval2<<<(NN + 7) / 8, 256>>>(0);
    k_agg2<<<(NN + 7) / 8, 256>>>(out);
}